// round 3
// baseline (speedup 1.0000x reference)
#include <cuda_runtime.h>

// out[row] = alpha(||p_row||, ||p_row * w||) * (p_row * w)
// alpha folds expmap0 -> mobius diag scaling -> project -> logmap0.
// 2 rows per warp: doubles front-batched MLP and interleaves the two
// independent scalar (shuffle+transcendental) tails.

#define NCOLS 512
#define WARPS_PER_BLOCK 8
#define ROWS_PER_WARP 2

__device__ __forceinline__ float row_alpha(float s1, float s2)
{
    const float SQRT_C = 0.1f;
    const float EPS    = 1e-5f;
    const float MIN_N  = 1e-5f;

    float n1 = sqrtf(s1);                 // ||p||
    float n2 = sqrtf(s2);                 // ||p*w||

    // expmap0: x = s * p
    float u_norm = fmaxf(n1, MIN_N);
    float su = SQRT_C * u_norm;
    float s = tanhf(su) / su;

    // mobius diag scaling
    float x_norm  = fmaxf(s * n1, MIN_N);
    float mx_norm = s * n2;               // NOT clamped (matches torch)
    float cx = fminf(fmaxf(SQRT_C * x_norm, -1.0f + EPS), 1.0f - EPS);
    float at = atanhf(cx);
    float tn = tanhf((mx_norm / x_norm) * at);
    float beta = tn * s / (mx_norm * SQRT_C);   // res = beta * (p*w)
    float res_norm = tn / SQRT_C;               // ||res||

    // project
    float rn = fmaxf(res_norm, MIN_N);
    float maxnorm = (1.0f - 0.001f) / SQRT_C;
    float gamma = (rn > maxnorm) ? (maxnorm / rn) : 1.0f;

    // logmap0
    float y_norm = fmaxf(gamma * res_norm, MIN_N);
    float cy = fminf(fmaxf(SQRT_C * y_norm, -1.0f + EPS), 1.0f - EPS);
    float at2 = atanhf(cy);
    return gamma * beta * at2 / (y_norm * SQRT_C);
}

__global__ __launch_bounds__(WARPS_PER_BLOCK * 32)
void hyp_adapter_kernel(const float* __restrict__ params,
                        const float* __restrict__ weights,
                        float* __restrict__ out,
                        int nrows)
{
    const int warp_id = (blockIdx.x * (WARPS_PER_BLOCK * 32) + threadIdx.x) >> 5;
    const int lane = threadIdx.x & 31;
    const int row0 = warp_id * ROWS_PER_WARP;
    if (row0 >= nrows) return;

    const float4* __restrict__ pr0 = reinterpret_cast<const float4*>(params) +
                                     (size_t)row0 * (NCOLS / 4);
    const float4* __restrict__ w4 = reinterpret_cast<const float4*>(weights);

    float4 va[4], vb[4], wv[4];

    // Front-batch everything: 8 param LDG.128 + 4 weight LDG.128 in flight.
#pragma unroll
    for (int j = 0; j < 4; ++j) va[j] = pr0[j * 32 + lane];
#pragma unroll
    for (int j = 0; j < 4; ++j) vb[j] = pr0[(NCOLS / 4) + j * 32 + lane];
#pragma unroll
    for (int j = 0; j < 4; ++j) wv[j] = __ldg(&w4[j * 32 + lane]);

    float a1 = 0.0f, a2 = 0.0f;   // row0: sum p^2, sum (p*w)^2
    float b1 = 0.0f, b2 = 0.0f;   // row1
#pragma unroll
    for (int j = 0; j < 4; ++j) {
        float4 a = va[j], b = vb[j], w = wv[j];
        a1 = fmaf(a.x, a.x, a1); a1 = fmaf(a.y, a.y, a1);
        a1 = fmaf(a.z, a.z, a1); a1 = fmaf(a.w, a.w, a1);
        b1 = fmaf(b.x, b.x, b1); b1 = fmaf(b.y, b.y, b1);
        b1 = fmaf(b.z, b.z, b1); b1 = fmaf(b.w, b.w, b1);
        float m0 = a.x * w.x, m1 = a.y * w.y, m2 = a.z * w.z, m3 = a.w * w.w;
        a2 = fmaf(m0, m0, a2); a2 = fmaf(m1, m1, a2);
        a2 = fmaf(m2, m2, a2); a2 = fmaf(m3, m3, a2);
        float n0 = b.x * w.x, n1 = b.y * w.y, n2 = b.z * w.z, n3 = b.w * w.w;
        b2 = fmaf(n0, n0, b2); b2 = fmaf(n1, n1, b2);
        b2 = fmaf(n2, n2, b2); b2 = fmaf(n3, n3, b2);
    }

    // Interleaved shuffle reductions: 4 independent chains.
#pragma unroll
    for (int off = 16; off > 0; off >>= 1) {
        a1 += __shfl_xor_sync(0xFFFFFFFFu, a1, off);
        b1 += __shfl_xor_sync(0xFFFFFFFFu, b1, off);
        a2 += __shfl_xor_sync(0xFFFFFFFFu, a2, off);
        b2 += __shfl_xor_sync(0xFFFFFFFFu, b2, off);
    }

    float alphaA = row_alpha(a1, a2);
    float alphaB = row_alpha(b1, b2);

    float4* __restrict__ or0 = reinterpret_cast<float4*>(out) +
                               (size_t)row0 * (NCOLS / 4);
#pragma unroll
    for (int j = 0; j < 4; ++j) {
        float4 a = va[j], w = wv[j];
        float4 o;
        o.x = alphaA * (a.x * w.x);
        o.y = alphaA * (a.y * w.y);
        o.z = alphaA * (a.z * w.z);
        o.w = alphaA * (a.w * w.w);
        or0[j * 32 + lane] = o;
    }
#pragma unroll
    for (int j = 0; j < 4; ++j) {
        float4 b = vb[j], w = wv[j];
        float4 o;
        o.x = alphaB * (b.x * w.x);
        o.y = alphaB * (b.y * w.y);
        o.z = alphaB * (b.z * w.z);
        o.w = alphaB * (b.w * w.w);
        or0[(NCOLS / 4) + j * 32 + lane] = o;
    }
}

extern "C" void kernel_launch(void* const* d_in, const int* in_sizes, int n_in,
                              void* d_out, int out_size)
{
    const float* params  = (const float*)d_in[0];
    const float* weights = (const float*)d_in[1];
    float* out = (float*)d_out;

    int nrows = in_sizes[0] / NCOLS;   // 131072
    int rows_per_block = WARPS_PER_BLOCK * ROWS_PER_WARP;
    int blocks = (nrows + rows_per_block - 1) / rows_per_block;

    hyp_adapter_kernel<<<blocks, WARPS_PER_BLOCK * 32>>>(params, weights, out, nrows);
}

// round 4
// speedup vs baseline: 1.0163x; 1.0163x over previous
#include <cuda_runtime.h>

// out[row] = alpha(||p||, ||p*w||) * (p*w), alpha folding expmap0 ->
// mobius diag -> project -> logmap0.
// Register-minimal: only m = p*w is held across the scalar tail (16 regs);
// p is consumed into s1 at load, weights stay L1-hot. Fast MUFU-based
// tanh/atanh shorten the serialized per-row tail.

#define NCOLS 512
#define WARPS_PER_BLOCK 8

__device__ __forceinline__ float fast_tanh_pos(float x)
{
    // x >= 0. tanh(x) = (1 - e^-2x) / (1 + e^-2x)
    float t = __expf(-2.0f * x);
    return __fdividef(1.0f - t, 1.0f + t);
}

__device__ __forceinline__ float fast_atanh01(float x)
{
    // x in [0, 1-eps]. atanh(x) = 0.5 * ln((1+x)/(1-x))
    return 0.5f * __logf(__fdividef(1.0f + x, 1.0f - x));
}

__global__ __launch_bounds__(WARPS_PER_BLOCK * 32, 8)
void hyp_adapter_kernel(const float* __restrict__ params,
                        const float* __restrict__ weights,
                        float* __restrict__ out,
                        int nrows)
{
    const int warp_global = (blockIdx.x * (WARPS_PER_BLOCK * 32) + threadIdx.x) >> 5;
    const int lane = threadIdx.x & 31;
    if (warp_global >= nrows) return;

    const float4* __restrict__ prow = reinterpret_cast<const float4*>(params) +
                                      (size_t)warp_global * (NCOLS / 4);
    const float4* __restrict__ w4 = reinterpret_cast<const float4*>(weights);

    float4 m[4];               // p*w — the only vector state held through the tail
    float s1 = 0.0f;           // sum p^2
    float s2 = 0.0f;           // sum (p*w)^2

#pragma unroll
    for (int j = 0; j < 4; ++j) {
        float4 a = prow[j * 32 + lane];
        float4 w = __ldg(&w4[j * 32 + lane]);
        s1 = fmaf(a.x, a.x, s1);
        s1 = fmaf(a.y, a.y, s1);
        s1 = fmaf(a.z, a.z, s1);
        s1 = fmaf(a.w, a.w, s1);
        m[j].x = a.x * w.x;
        m[j].y = a.y * w.y;
        m[j].z = a.z * w.z;
        m[j].w = a.w * w.w;
        s2 = fmaf(m[j].x, m[j].x, s2);
        s2 = fmaf(m[j].y, m[j].y, s2);
        s2 = fmaf(m[j].z, m[j].z, s2);
        s2 = fmaf(m[j].w, m[j].w, s2);
    }

#pragma unroll
    for (int off = 16; off > 0; off >>= 1) {
        s1 += __shfl_xor_sync(0xFFFFFFFFu, s1, off);
        s2 += __shfl_xor_sync(0xFFFFFFFFu, s2, off);
    }

    const float SQRT_C = 0.1f;
    const float EPS    = 1e-5f;
    const float MIN_N  = 1e-5f;

    float n1 = sqrtf(s1);                 // ||p||
    float n2 = sqrtf(s2);                 // ||p*w||

    // expmap0: x = s * p
    float u_norm = fmaxf(n1, MIN_N);
    float su = SQRT_C * u_norm;
    float s = __fdividef(fast_tanh_pos(su), su);

    // mobius diag scaling
    float x_norm  = fmaxf(s * n1, MIN_N);
    float mx_norm = s * n2;               // NOT clamped (matches torch)
    float cx = fminf(fmaxf(SQRT_C * x_norm, -1.0f + EPS), 1.0f - EPS);
    float at = fast_atanh01(cx);
    float tn = fast_tanh_pos(__fdividef(mx_norm, x_norm) * at);
    float beta = __fdividef(tn * s, mx_norm * SQRT_C);  // res = beta * (p*w)
    float res_norm = tn * (1.0f / SQRT_C);              // ||res||

    // project
    float rn = fmaxf(res_norm, MIN_N);
    float maxnorm = (1.0f - 0.001f) / SQRT_C;
    float gamma = (rn > maxnorm) ? __fdividef(maxnorm, rn) : 1.0f;

    // logmap0
    float y_norm = fmaxf(gamma * res_norm, MIN_N);
    float cy = fminf(fmaxf(SQRT_C * y_norm, -1.0f + EPS), 1.0f - EPS);
    float at2 = fast_atanh01(cy);
    float alpha = __fdividef(gamma * beta * at2, y_norm * SQRT_C);

    float4* __restrict__ orow = reinterpret_cast<float4*>(out) +
                                (size_t)warp_global * (NCOLS / 4);
#pragma unroll
    for (int j = 0; j < 4; ++j) {
        float4 o;
        o.x = alpha * m[j].x;
        o.y = alpha * m[j].y;
        o.z = alpha * m[j].z;
        o.w = alpha * m[j].w;
        orow[j * 32 + lane] = o;
    }
}

extern "C" void kernel_launch(void* const* d_in, const int* in_sizes, int n_in,
                              void* d_out, int out_size)
{
    const float* params  = (const float*)d_in[0];
    const float* weights = (const float*)d_in[1];
    float* out = (float*)d_out;

    int nrows = in_sizes[0] / NCOLS;   // 131072
    int blocks = (nrows + WARPS_PER_BLOCK - 1) / WARPS_PER_BLOCK;

    hyp_adapter_kernel<<<blocks, WARPS_PER_BLOCK * 32>>>(params, weights, out, nrows);
}